// round 13
// baseline (speedup 1.0000x reference)
#include <cuda_runtime.h>
#include <cuda_fp16.h>
#include <cstdint>

// Problem constants
#define BATCH   2
#define TSEQ    2048
#define CDIM    1024
#define NHEADS  16
#define HDIM    64
#define QKVN    (3 * CDIM)  // 3072

// Scratch (allocation-free rule: __device__ globals)
__device__ __half g_qkv[(size_t)BATCH * TSEQ * 3 * CDIM];  // (B,T,3C) fp16, Q pre-scaled (incl. log2e)
__device__ __half g_att[(size_t)BATCH * TSEQ * CDIM];      // attn out fp16
__device__ __half g_xh[(size_t)BATCH * TSEQ * CDIM];       // x fp16
__device__ __half g_wqkvh[(size_t)CDIM * QKVN];            // w_qkv fp16
__device__ __half g_wprojh[(size_t)CDIM * CDIM];           // w_proj fp16

// ---------------------------------------------------------------------------
// Helpers
// ---------------------------------------------------------------------------
__device__ __forceinline__ uint32_t packh2(float lo, float hi) {
    uint32_t r;
    asm("cvt.rn.f16x2.f32 %0, %1, %2;" : "=r"(r) : "f"(hi), "f"(lo));
    return r;
}

__device__ __forceinline__ void mma16(float c[4], const uint32_t a[4], const uint32_t b[2]) {
    asm volatile(
        "mma.sync.aligned.m16n8k16.row.col.f32.f16.f16.f32 "
        "{%0,%1,%2,%3}, {%4,%5,%6,%7}, {%8,%9}, {%0,%1,%2,%3};\n"
        : "+f"(c[0]), "+f"(c[1]), "+f"(c[2]), "+f"(c[3])
        : "r"(a[0]), "r"(a[1]), "r"(a[2]), "r"(a[3]), "r"(b[0]), "r"(b[1]));
}

__device__ __forceinline__ void ldsm4(uint32_t r[4], uint32_t a) {
    asm volatile("ldmatrix.sync.aligned.m8n8.x4.shared.b16 {%0,%1,%2,%3}, [%4];"
                 : "=r"(r[0]), "=r"(r[1]), "=r"(r[2]), "=r"(r[3]) : "r"(a));
}
__device__ __forceinline__ void ldsm4t(uint32_t r[4], uint32_t a) {
    asm volatile("ldmatrix.sync.aligned.m8n8.x4.trans.shared.b16 {%0,%1,%2,%3}, [%4];"
                 : "=r"(r[0]), "=r"(r[1]), "=r"(r[2]), "=r"(r[3]) : "r"(a));
}

__device__ __forceinline__ void cpa16(uint32_t smaddr, const void* gptr) {
    asm volatile("cp.async.cg.shared.global [%0], [%1], 16;\n"
                 :: "r"(smaddr), "l"(gptr));
}
#define CP_COMMIT() asm volatile("cp.async.commit_group;\n" ::: "memory")
#define CP_WAITG(n) asm volatile("cp.async.wait_group %0;\n" :: "n"(n) : "memory")

// ---------------------------------------------------------------------------
// Pre-pass: fp32 -> fp16 (8 elems/thread)
// ---------------------------------------------------------------------------
__global__ __launch_bounds__(256) void f16_convert_kernel(
    const float* __restrict__ in, __half* __restrict__ out, int n8)
{
    const int i = blockIdx.x * blockDim.x + threadIdx.x;
    if (i < n8) {
        const float4 v0 = ((const float4*)in)[2 * i];
        const float4 v1 = ((const float4*)in)[2 * i + 1];
        uint4 u;
        u.x = packh2(v0.x, v0.y);  u.y = packh2(v0.z, v0.w);
        u.z = packh2(v1.x, v1.y);  u.w = packh2(v1.z, v1.w);
        ((uint4*)out)[i] = u;
    }
}

// ---------------------------------------------------------------------------
// FP16 tensor-core GEMM (fp32 accumulate) — unchanged from R12 (87.8 us).
// 128x128x64 CTA K-slab, 8 warps (warp tile 32x64), 3-stage cp.async pipeline.
// qkv_mode=1: C is half*, first CDIM cols (Q) pre-scaled by 0.125*log2(e).
// qkv_mode=0: C is float*.
// ---------------------------------------------------------------------------
#define QSCALE (0.125f * 1.44269504088896f)   // D^-0.5 * log2(e)

#define ASTRH 72                     // 64 data + 8 pad halfs per A row
#define ASZH  (128 * ASTRH)          // 9216 halfs
#define BSTRH 136                    // 128 data + 8 pad halfs per B row
#define BSZH  (64 * BSTRH)           // 8704 halfs
#define STGH  (ASZH + BSZH)          // 17920 halfs/stage
#define NSTG  3
#define GEMM_SMEM (NSTG * STGH * 2)  // 107520 bytes

__global__ __launch_bounds__(256, 2) void gemm_f16_kernel(
    const __half* __restrict__ A, const __half* __restrict__ B,
    const float* __restrict__ bias, void* __restrict__ Cout,
    int M, int N, int K, int qkv_mode)
{
    extern __shared__ __half sm[];
    const uint32_t smb = (uint32_t)__cvta_generic_to_shared(sm);

    const int tid  = threadIdx.x;
    const int lane = tid & 31;
    const int wid  = tid >> 5;
    const int g    = lane >> 2;
    const int tig  = lane & 3;
    const int wm   = (wid & 3) * 32;
    const int wn   = (wid >> 2) * 64;

    const int bm = blockIdx.y * 128;
    const int bn = blockIdx.x * 128;

    const int lrow = lane & 15;
    const int lhi8 = (lane >> 4) << 3;
    const uint32_t a_off = (uint32_t)(((wm + lrow) * ASTRH + lhi8) * 2);
    const uint32_t b_off = (uint32_t)((ASZH + lrow * BSTRH + wn + lhi8) * 2);

    float acc[2][8][4];
    #pragma unroll
    for (int mt = 0; mt < 2; mt++)
        #pragma unroll
        for (int nt = 0; nt < 8; nt++)
            #pragma unroll
            for (int i = 0; i < 4; i++) acc[mt][nt][i] = 0.0f;

    #define ISSUE(s, k0)                                                       \
        do {                                                                   \
            const uint32_t sb = smb + (uint32_t)((s) * STGH * 2);              \
            _Pragma("unroll")                                                  \
            for (int c = tid; c < 1024; c += 256) {                            \
                const int m_ = c >> 3, kc_ = (c & 7) << 3;                     \
                cpa16(sb + (uint32_t)((m_ * ASTRH + kc_) * 2),                 \
                      &A[(size_t)(bm + m_) * K + (k0) + kc_]);                 \
            }                                                                  \
            _Pragma("unroll")                                                  \
            for (int c = tid; c < 1024; c += 256) {                            \
                const int k_ = c >> 4, nc_ = (c & 15) << 3;                    \
                cpa16(sb + (uint32_t)((ASZH + k_ * BSTRH + nc_) * 2),          \
                      &B[(size_t)((k0) + k_) * N + bn + nc_]);                 \
            }                                                                  \
        } while (0)

    const int ns = K / 64;           // 16 slabs
    ISSUE(0, 0);   CP_COMMIT();
    ISSUE(1, 64);  CP_COMMIT();

    for (int i = 0; i < ns; i++) {
        const int cur = i % 3;
        CP_WAITG(1);
        __syncthreads();

        if (i + 2 < ns) ISSUE((i + 2) % 3, (i + 2) * 64);
        CP_COMMIT();

        const uint32_t sb = smb + (uint32_t)(cur * STGH * 2);
        const uint32_t ab = sb + a_off;
        const uint32_t bb = sb + b_off;

        #pragma unroll
        for (int kk = 0; kk < 64; kk += 16) {
            uint32_t a0[4], a1[4];
            ldsm4(a0, ab + (uint32_t)(kk * 2));
            ldsm4(a1, ab + (uint32_t)(16 * ASTRH * 2 + kk * 2));
            #pragma unroll
            for (int j = 0; j < 4; j++) {
                uint32_t bf[4];
                ldsm4t(bf, bb + (uint32_t)(kk * BSTRH * 2 + j * 32));
                mma16(acc[0][2 * j],     a0, bf);
                mma16(acc[1][2 * j],     a1, bf);
                mma16(acc[0][2 * j + 1], a0, bf + 2);
                mma16(acc[1][2 * j + 1], a1, bf + 2);
            }
        }
    }
    #undef ISSUE

    // ---- epilogue ----
    #pragma unroll
    for (int mt = 0; mt < 2; mt++) {
        const int r0 = bm + wm + mt * 16 + g;
        #pragma unroll
        for (int nt = 0; nt < 8; nt++) {
            const int cc = bn + wn + nt * 8 + 2 * tig;
            const float2 bi = *(const float2*)&bias[cc];
            const float v00 = acc[mt][nt][0] + bi.x, v01 = acc[mt][nt][1] + bi.y;
            const float v10 = acc[mt][nt][2] + bi.x, v11 = acc[mt][nt][3] + bi.y;
            if (qkv_mode) {
                const float s = (cc < CDIM) ? QSCALE : 1.0f;  // Q pre-scale (base-2 domain)
                __half* C = (__half*)Cout;
                *(uint32_t*)&C[(size_t)r0 * N + cc]       = packh2(v00 * s, v01 * s);
                *(uint32_t*)&C[(size_t)(r0 + 8) * N + cc] = packh2(v10 * s, v11 * s);
            } else {
                float* C = (float*)Cout;
                float2 u0 = { v00, v01 }, u1 = { v10, v11 };
                *(float2*)&C[(size_t)r0 * N + cc]       = u0;
                *(float2*)&C[(size_t)(r0 + 8) * N + cc] = u1;
            }
        }
    }
}

// ---------------------------------------------------------------------------
// FP16 mma.sync flash attention, v2: 4 warps x 32 q-rows (2 m-tiles) = 128
// queries/CTA. K/V B-fragment smem traffic HALVED per MAC (B-frags shared
// across both m-tiles). Keys processed in two 32-key halves per 64-key tile
// to bound live registers. 3-stage cp.async pipeline, one sync per tile,
// exp2-domain softmax (log2e folded into Q). Q staged through stage-buf 2.
// ---------------------------------------------------------------------------
#define KSTR 72                      // halfs per K/V row (64 + 8 pad)
#define KVH  (64 * KSTR)             // 4608 halfs per tensor
#define FBH  (2 * KVH)               // 9216 halfs per stage (K + V)
#define NKT  (TSEQ / 64)
#define FLASH_SMEM (3 * FBH * 2)     // 55296 B

__global__ __launch_bounds__(128, 2) void flash_f16_kernel(
    const __half* __restrict__ qkv, __half* __restrict__ out)
{
    extern __shared__ __half fsm[];
    const uint32_t smb = (uint32_t)__cvta_generic_to_shared(fsm);

    const int b   = blockIdx.z;
    const int h   = blockIdx.y;
    const int q0  = blockIdx.x * 128;
    const int tid = threadIdx.x;
    const int w    = tid >> 5;       // 0..3
    const int lane = tid & 31;
    const int g    = lane >> 2;
    const int tig  = lane & 3;

    #define STAGE_KV(buf_idx, kt)                                              \
        do {                                                                   \
            const uint32_t kb_ = smb + (uint32_t)((buf_idx) * FBH * 2);        \
            const uint32_t vb_ = kb_ + (uint32_t)(KVH * 2);                    \
            for (int i = tid; i < 512; i += 128) {                             \
                const int row = i >> 3;                                        \
                const int c8  = (i & 7) << 3;                                  \
                const size_t base =                                            \
                    ((size_t)(b * TSEQ + (kt) + row)) * QKVN + h * HDIM + c8;  \
                cpa16(kb_ + (uint32_t)((row * KSTR + c8) * 2),                 \
                      &qkv[base + CDIM]);                                      \
                cpa16(vb_ + (uint32_t)((row * KSTR + c8) * 2),                 \
                      &qkv[base + 2 * CDIM]);                                  \
            }                                                                  \
        } while (0)

    // Overlap first K/V stages with Q prep
    STAGE_KV(0, 0);   CP_COMMIT();
    STAGE_KV(1, 64);  CP_COMMIT();

    // ---- stage Q (128 rows) through stage-buffer 2 (9216 halfs = FBH) ----
    {
        __half* qs = fsm + 2 * FBH;
        for (int i = tid; i < 1024; i += 128) {
            const int row = i >> 3;
            const int c8  = (i & 7) << 3;
            *(uint4*)&qs[row * KSTR + c8] =
                *(const uint4*)&qkv[((size_t)(b * TSEQ + q0 + row)) * QKVN + h * HDIM + c8];
        }
    }
    __syncthreads();

    const int lrow = lane & 15;
    const int lhi8 = (lane >> 4) << 3;
    uint32_t qf[2][4][4];            // [m-tile][d-step][frag]
    #pragma unroll
    for (int mt = 0; mt < 2; mt++) {
        const uint32_t qb = smb + (uint32_t)(2 * FBH * 2) +
                            (uint32_t)(((w * 32 + mt * 16 + lrow) * KSTR + lhi8) * 2);
        #pragma unroll
        for (int ds = 0; ds < 4; ds++) ldsm4(qf[mt][ds], qb + (uint32_t)(ds * 32));
    }

    CP_WAITG(1);        // stage 0 landed (per-thread)
    __syncthreads();    // visible to all; everyone's Q ldsm done -> buf2 free

    const int krow_off = ((lane >> 4) << 3) + (lane & 7);
    const int kdsel    = ((lane >> 3) & 1) << 3;
    const int vrow_off = (((lane >> 3) & 1) << 3) + (lane & 7);
    const int vdsel    = (lane >> 4) << 3;

    float o[2][8][4];
    #pragma unroll
    for (int mt = 0; mt < 2; mt++)
        #pragma unroll
        for (int nt = 0; nt < 8; nt++)
            #pragma unroll
            for (int i = 0; i < 4; i++) o[mt][nt][i] = 0.0f;
    float mrow[2][2] = { {-1e30f, -1e30f}, {-1e30f, -1e30f} };
    float lrow_[2][2] = { {0.0f, 0.0f}, {0.0f, 0.0f} };

    for (int it = 0; it < NKT; it++) {
        if (it + 2 < NKT) STAGE_KV((it + 2) % 3, (it + 2) * 64);
        CP_COMMIT();    // always commit to keep group accounting fixed

        const uint32_t ksb = smb + (uint32_t)((it % 3) * FBH * 2);
        const uint32_t vsb = ksb + (uint32_t)(KVH * 2);
        const uint32_t kbase = ksb + (uint32_t)((krow_off * KSTR + kdsel) * 2);
        const uint32_t vbase = vsb + (uint32_t)((vrow_off * KSTR + vdsel) * 2);

        #pragma unroll
        for (int hk = 0; hk < 2; hk++) {      // two 32-key halves
            // ---- S = Q @ K^T (base-2 logits), 32q x 32k ----
            float sv[2][4][4];
            #pragma unroll
            for (int mt = 0; mt < 2; mt++)
                #pragma unroll
                for (int nt = 0; nt < 4; nt++)
                    #pragma unroll
                    for (int i = 0; i < 4; i++) sv[mt][nt][i] = 0.0f;

            #pragma unroll
            for (int ds = 0; ds < 4; ds++) {
                #pragma unroll
                for (int j = 0; j < 2; j++) {
                    uint32_t bf[4];   // 16 keys x 16 d
                    ldsm4(bf, kbase +
                          (uint32_t)(((hk * 32 + j * 16) * KSTR + ds * 16) * 2));
                    mma16(sv[0][2 * j],     qf[0][ds], bf);
                    mma16(sv[0][2 * j + 1], qf[0][ds], bf + 2);
                    mma16(sv[1][2 * j],     qf[1][ds], bf);
                    mma16(sv[1][2 * j + 1], qf[1][ds], bf + 2);
                }
            }

            // ---- online softmax (exp2 domain), per m-tile ----
            uint32_t pv[2][4][2];
            #pragma unroll
            for (int mt = 0; mt < 2; mt++) {
                float rmax0 = -1e30f, rmax1 = -1e30f;
                #pragma unroll
                for (int nt = 0; nt < 4; nt++) {
                    rmax0 = fmaxf(rmax0, fmaxf(sv[mt][nt][0], sv[mt][nt][1]));
                    rmax1 = fmaxf(rmax1, fmaxf(sv[mt][nt][2], sv[mt][nt][3]));
                }
                rmax0 = fmaxf(rmax0, __shfl_xor_sync(0xffffffffu, rmax0, 1));
                rmax0 = fmaxf(rmax0, __shfl_xor_sync(0xffffffffu, rmax0, 2));
                rmax1 = fmaxf(rmax1, __shfl_xor_sync(0xffffffffu, rmax1, 1));
                rmax1 = fmaxf(rmax1, __shfl_xor_sync(0xffffffffu, rmax1, 2));

                const float mn0 = fmaxf(mrow[mt][0], rmax0);
                const float mn1 = fmaxf(mrow[mt][1], rmax1);
                const float cr0 = exp2f(mrow[mt][0] - mn0);
                const float cr1 = exp2f(mrow[mt][1] - mn1);
                mrow[mt][0] = mn0; mrow[mt][1] = mn1;

                float ls0 = 0.0f, ls1 = 0.0f;
                #pragma unroll
                for (int nt = 0; nt < 4; nt++) {
                    const float p0 = exp2f(sv[mt][nt][0] - mn0);
                    const float p1 = exp2f(sv[mt][nt][1] - mn0);
                    const float p2 = exp2f(sv[mt][nt][2] - mn1);
                    const float p3 = exp2f(sv[mt][nt][3] - mn1);
                    ls0 += p0 + p1;  ls1 += p2 + p3;
                    pv[mt][nt][0] = packh2(p0, p1);   // P C-frag == PV A-frag
                    pv[mt][nt][1] = packh2(p2, p3);
                }
                ls0 += __shfl_xor_sync(0xffffffffu, ls0, 1);
                ls0 += __shfl_xor_sync(0xffffffffu, ls0, 2);
                ls1 += __shfl_xor_sync(0xffffffffu, ls1, 1);
                ls1 += __shfl_xor_sync(0xffffffffu, ls1, 2);
                lrow_[mt][0] = lrow_[mt][0] * cr0 + ls0;
                lrow_[mt][1] = lrow_[mt][1] * cr1 + ls1;

                #pragma unroll
                for (int nt = 0; nt < 8; nt++) {
                    o[mt][nt][0] *= cr0; o[mt][nt][1] *= cr0;
                    o[mt][nt][2] *= cr1; o[mt][nt][3] *= cr1;
                }
            }

            // ---- O += P @ V (B-frags shared across both m-tiles) ----
            #pragma unroll
            for (int kg = 0; kg < 2; kg++) {  // 16-key groups within half
                const uint32_t a0[4] = { pv[0][2 * kg][0], pv[0][2 * kg][1],
                                         pv[0][2 * kg + 1][0], pv[0][2 * kg + 1][1] };
                const uint32_t a1[4] = { pv[1][2 * kg][0], pv[1][2 * kg][1],
                                         pv[1][2 * kg + 1][0], pv[1][2 * kg + 1][1] };
                #pragma unroll
                for (int t = 0; t < 4; t++) {
                    uint32_t bf[4];   // 16 keys x 16 d (trans)
                    ldsm4t(bf, vbase +
                           (uint32_t)(((hk * 32 + kg * 16) * KSTR + t * 16) * 2));
                    mma16(o[0][2 * t],     a0, bf);
                    mma16(o[0][2 * t + 1], a0, bf + 2);
                    mma16(o[1][2 * t],     a1, bf);
                    mma16(o[1][2 * t + 1], a1, bf + 2);
                }
            }
        }

        CP_WAITG(1);        // stage it+1 landed (per-thread)
        __syncthreads();    // single barrier: visibility + buffer-reuse order
    }
    #undef STAGE_KV

    // ---- epilogue: fp16 att for proj GEMM ----
    #pragma unroll
    for (int mt = 0; mt < 2; mt++) {
        const float i0 = 1.0f / lrow_[mt][0];
        const float i1 = 1.0f / lrow_[mt][1];
        const int r0 = q0 + w * 32 + mt * 16 + g;
        #pragma unroll
        for (int nt = 0; nt < 8; nt++) {
            const int cc = h * HDIM + nt * 8 + 2 * tig;
            *(uint32_t*)&out[((size_t)(b * TSEQ + r0)) * CDIM + cc] =
                packh2(o[mt][nt][0] * i0, o[mt][nt][1] * i0);
            *(uint32_t*)&out[((size_t)(b * TSEQ + r0 + 8)) * CDIM + cc] =
                packh2(o[mt][nt][2] * i1, o[mt][nt][3] * i1);
        }
    }
}

// ---------------------------------------------------------------------------
// Launch
// ---------------------------------------------------------------------------
extern "C" void kernel_launch(void* const* d_in, const int* in_sizes, int n_in,
                              void* d_out, int out_size)
{
    const float* x      = (const float*)d_in[0];
    const float* w_qkv  = (const float*)d_in[1];
    const float* b_qkv  = (const float*)d_in[2];
    const float* w_proj = (const float*)d_in[3];
    const float* b_proj = (const float*)d_in[4];
    float* out = (float*)d_out;

    __half* qkv;   cudaGetSymbolAddress((void**)&qkv,   g_qkv);
    __half* att;   cudaGetSymbolAddress((void**)&att,   g_att);
    __half* xh;    cudaGetSymbolAddress((void**)&xh,    g_xh);
    __half* wqkvh; cudaGetSymbolAddress((void**)&wqkvh, g_wqkvh);
    __half* wprjh; cudaGetSymbolAddress((void**)&wprjh, g_wprojh);

    cudaFuncSetAttribute(gemm_f16_kernel,
                         cudaFuncAttributeMaxDynamicSharedMemorySize, GEMM_SMEM);
    cudaFuncSetAttribute(flash_f16_kernel,
                         cudaFuncAttributeMaxDynamicSharedMemorySize, FLASH_SMEM);

    const int M = BATCH * TSEQ;   // 4096

    // 0) fp16 pre-conversion
    {
        const int n8x = M * CDIM / 8;        // 524288
        const int n8q = CDIM * QKVN / 8;     // 393216
        const int n8p = CDIM * CDIM / 8;     // 131072
        f16_convert_kernel<<<(n8x + 255) / 256, 256>>>(x, xh, n8x);
        f16_convert_kernel<<<(n8q + 255) / 256, 256>>>(w_qkv, wqkvh, n8q);
        f16_convert_kernel<<<(n8p + 255) / 256, 256>>>(w_proj, wprjh, n8p);
    }
    {   // 1) QKV projection (fp16 out, Q pre-scaled incl. log2e)
        dim3 grid(QKVN / 128, M / 128);   // (24, 32)
        gemm_f16_kernel<<<grid, 256, GEMM_SMEM>>>(xh, wqkvh, b_qkv, qkv, M, QKVN, CDIM, 1);
    }
    {   // 2) Flash attention (fp16 mma.sync, 32 q-rows/warp, halved K/V smem traffic)
        dim3 grid(TSEQ / 128, NHEADS, BATCH);   // (16, 16, 2)
        flash_f16_kernel<<<grid, 128, FLASH_SMEM>>>(qkv, att);
    }
    {   // 3) Output projection (fp32 out)
        dim3 grid(CDIM / 128, M / 128);   // (8, 32)
        gemm_f16_kernel<<<grid, 256, GEMM_SMEM>>>(att, wprjh, b_proj, out, M, CDIM, CDIM, 0);
    }
}

// round 14
// speedup vs baseline: 1.0695x; 1.0695x over previous
#include <cuda_runtime.h>
#include <cuda_fp16.h>
#include <cstdint>

// Problem constants
#define BATCH   2
#define TSEQ    2048
#define CDIM    1024
#define NHEADS  16
#define HDIM    64
#define QKVN    (3 * CDIM)  // 3072

// Scratch (allocation-free rule: __device__ globals)
__device__ __half g_qkv[(size_t)BATCH * TSEQ * 3 * CDIM];  // (B,T,3C) fp16, Q pre-scaled (incl. log2e)
__device__ __half g_att[(size_t)BATCH * TSEQ * CDIM];      // attn out fp16
__device__ __half g_xh[(size_t)BATCH * TSEQ * CDIM];       // x fp16
__device__ __half g_wqkvh[(size_t)CDIM * QKVN];            // w_qkv fp16
__device__ __half g_wprojh[(size_t)CDIM * CDIM];           // w_proj fp16

// ---------------------------------------------------------------------------
// Helpers
// ---------------------------------------------------------------------------
__device__ __forceinline__ uint32_t packh2(float lo, float hi) {
    uint32_t r;
    asm("cvt.rn.f16x2.f32 %0, %1, %2;" : "=r"(r) : "f"(hi), "f"(lo));
    return r;
}

__device__ __forceinline__ void mma16(float c[4], const uint32_t a[4], const uint32_t b[2]) {
    asm volatile(
        "mma.sync.aligned.m16n8k16.row.col.f32.f16.f16.f32 "
        "{%0,%1,%2,%3}, {%4,%5,%6,%7}, {%8,%9}, {%0,%1,%2,%3};\n"
        : "+f"(c[0]), "+f"(c[1]), "+f"(c[2]), "+f"(c[3])
        : "r"(a[0]), "r"(a[1]), "r"(a[2]), "r"(a[3]), "r"(b[0]), "r"(b[1]));
}

__device__ __forceinline__ void ldsm4(uint32_t r[4], uint32_t a) {
    asm volatile("ldmatrix.sync.aligned.m8n8.x4.shared.b16 {%0,%1,%2,%3}, [%4];"
                 : "=r"(r[0]), "=r"(r[1]), "=r"(r[2]), "=r"(r[3]) : "r"(a));
}
__device__ __forceinline__ void ldsm4t(uint32_t r[4], uint32_t a) {
    asm volatile("ldmatrix.sync.aligned.m8n8.x4.trans.shared.b16 {%0,%1,%2,%3}, [%4];"
                 : "=r"(r[0]), "=r"(r[1]), "=r"(r[2]), "=r"(r[3]) : "r"(a));
}

__device__ __forceinline__ void cpa16(uint32_t smaddr, const void* gptr) {
    asm volatile("cp.async.cg.shared.global [%0], [%1], 16;\n"
                 :: "r"(smaddr), "l"(gptr));
}
#define CP_COMMIT() asm volatile("cp.async.commit_group;\n" ::: "memory")
#define CP_WAITG(n) asm volatile("cp.async.wait_group %0;\n" :: "n"(n) : "memory")

// ---------------------------------------------------------------------------
// Pre-pass: fused fp32 -> fp16 conversion of x, w_qkv, w_proj (one launch)
// ---------------------------------------------------------------------------
#define N8X (BATCH * TSEQ * CDIM / 8)   // 524288
#define N8Q (CDIM * QKVN / 8)           // 393216
#define N8P (CDIM * CDIM / 8)           // 131072

__global__ __launch_bounds__(256) void f16_convert_all_kernel(
    const float* __restrict__ x, const float* __restrict__ wq,
    const float* __restrict__ wp,
    __half* __restrict__ xh, __half* __restrict__ wqh, __half* __restrict__ wph)
{
    int i = blockIdx.x * blockDim.x + threadIdx.x;
    const float* in;
    __half* out;
    if (i < N8X)                  { in = x;  out = xh; }
    else if (i < N8X + N8Q)       { in = wq; out = wqh; i -= N8X; }
    else if (i < N8X + N8Q + N8P) { in = wp; out = wph; i -= (N8X + N8Q); }
    else return;

    const float4 v0 = ((const float4*)in)[2 * i];
    const float4 v1 = ((const float4*)in)[2 * i + 1];
    uint4 u;
    u.x = packh2(v0.x, v0.y);  u.y = packh2(v0.z, v0.w);
    u.z = packh2(v1.x, v1.y);  u.w = packh2(v1.z, v1.w);
    ((uint4*)out)[i] = u;
}

// ---------------------------------------------------------------------------
// FP16 tensor-core GEMM (fp32 accumulate) — unchanged from R12 (87.8 us).
// 128x128x64 CTA K-slab, 8 warps (warp tile 32x64), 3-stage cp.async pipeline.
// qkv_mode=1: C is half*, first CDIM cols (Q) pre-scaled by 0.125*log2(e).
// qkv_mode=0: C is float*.
// ---------------------------------------------------------------------------
#define QSCALE (0.125f * 1.44269504088896f)   // D^-0.5 * log2(e)

#define ASTRH 72                     // 64 data + 8 pad halfs per A row
#define ASZH  (128 * ASTRH)          // 9216 halfs
#define BSTRH 136                    // 128 data + 8 pad halfs per B row
#define BSZH  (64 * BSTRH)           // 8704 halfs
#define STGH  (ASZH + BSZH)          // 17920 halfs/stage
#define NSTG  3
#define GEMM_SMEM (NSTG * STGH * 2)  // 107520 bytes

__global__ __launch_bounds__(256, 2) void gemm_f16_kernel(
    const __half* __restrict__ A, const __half* __restrict__ B,
    const float* __restrict__ bias, void* __restrict__ Cout,
    int M, int N, int K, int qkv_mode)
{
    extern __shared__ __half sm[];
    const uint32_t smb = (uint32_t)__cvta_generic_to_shared(sm);

    const int tid  = threadIdx.x;
    const int lane = tid & 31;
    const int wid  = tid >> 5;
    const int g    = lane >> 2;
    const int tig  = lane & 3;
    const int wm   = (wid & 3) * 32;
    const int wn   = (wid >> 2) * 64;

    const int bm = blockIdx.y * 128;
    const int bn = blockIdx.x * 128;

    const int lrow = lane & 15;
    const int lhi8 = (lane >> 4) << 3;
    const uint32_t a_off = (uint32_t)(((wm + lrow) * ASTRH + lhi8) * 2);
    const uint32_t b_off = (uint32_t)((ASZH + lrow * BSTRH + wn + lhi8) * 2);

    float acc[2][8][4];
    #pragma unroll
    for (int mt = 0; mt < 2; mt++)
        #pragma unroll
        for (int nt = 0; nt < 8; nt++)
            #pragma unroll
            for (int i = 0; i < 4; i++) acc[mt][nt][i] = 0.0f;

    #define ISSUE(s, k0)                                                       \
        do {                                                                   \
            const uint32_t sb = smb + (uint32_t)((s) * STGH * 2);              \
            _Pragma("unroll")                                                  \
            for (int c = tid; c < 1024; c += 256) {                            \
                const int m_ = c >> 3, kc_ = (c & 7) << 3;                     \
                cpa16(sb + (uint32_t)((m_ * ASTRH + kc_) * 2),                 \
                      &A[(size_t)(bm + m_) * K + (k0) + kc_]);                 \
            }                                                                  \
            _Pragma("unroll")                                                  \
            for (int c = tid; c < 1024; c += 256) {                            \
                const int k_ = c >> 4, nc_ = (c & 15) << 3;                    \
                cpa16(sb + (uint32_t)((ASZH + k_ * BSTRH + nc_) * 2),          \
                      &B[(size_t)((k0) + k_) * N + bn + nc_]);                 \
            }                                                                  \
        } while (0)

    const int ns = K / 64;           // 16 slabs
    ISSUE(0, 0);   CP_COMMIT();
    ISSUE(1, 64);  CP_COMMIT();

    for (int i = 0; i < ns; i++) {
        const int cur = i % 3;
        CP_WAITG(1);
        __syncthreads();

        if (i + 2 < ns) ISSUE((i + 2) % 3, (i + 2) * 64);
        CP_COMMIT();

        const uint32_t sb = smb + (uint32_t)(cur * STGH * 2);
        const uint32_t ab = sb + a_off;
        const uint32_t bb = sb + b_off;

        #pragma unroll
        for (int kk = 0; kk < 64; kk += 16) {
            uint32_t a0[4], a1[4];
            ldsm4(a0, ab + (uint32_t)(kk * 2));
            ldsm4(a1, ab + (uint32_t)(16 * ASTRH * 2 + kk * 2));
            #pragma unroll
            for (int j = 0; j < 4; j++) {
                uint32_t bf[4];
                ldsm4t(bf, bb + (uint32_t)(kk * BSTRH * 2 + j * 32));
                mma16(acc[0][2 * j],     a0, bf);
                mma16(acc[1][2 * j],     a1, bf);
                mma16(acc[0][2 * j + 1], a0, bf + 2);
                mma16(acc[1][2 * j + 1], a1, bf + 2);
            }
        }
    }
    #undef ISSUE

    // ---- epilogue ----
    #pragma unroll
    for (int mt = 0; mt < 2; mt++) {
        const int r0 = bm + wm + mt * 16 + g;
        #pragma unroll
        for (int nt = 0; nt < 8; nt++) {
            const int cc = bn + wn + nt * 8 + 2 * tig;
            const float2 bi = *(const float2*)&bias[cc];
            const float v00 = acc[mt][nt][0] + bi.x, v01 = acc[mt][nt][1] + bi.y;
            const float v10 = acc[mt][nt][2] + bi.x, v11 = acc[mt][nt][3] + bi.y;
            if (qkv_mode) {
                const float s = (cc < CDIM) ? QSCALE : 1.0f;  // Q pre-scale (base-2 domain)
                __half* C = (__half*)Cout;
                *(uint32_t*)&C[(size_t)r0 * N + cc]       = packh2(v00 * s, v01 * s);
                *(uint32_t*)&C[(size_t)(r0 + 8) * N + cc] = packh2(v10 * s, v11 * s);
            } else {
                float* C = (float*)Cout;
                float2 u0 = { v00, v01 }, u1 = { v10, v11 };
                *(float2*)&C[(size_t)r0 * N + cc]       = u0;
                *(float2*)&C[(size_t)(r0 + 8) * N + cc] = u1;
            }
        }
    }
}

// ---------------------------------------------------------------------------
// FP16 mma.sync flash attention (R12 body): 128 thr, 64 queries/CTA,
// 3-stage cp.async K/V pipeline, ONE __syncthreads per key-tile,
// exp2-domain softmax (log2e folded into Q). Q staged through stage-buf 2.
// NEW: __launch_bounds__(128, 4) caps regs at 128 -> 4 CTAs/SM
// (4 x 55296 B = 221184 B smem fits), doubling occupancy to 16 warps/SM.
// ---------------------------------------------------------------------------
#define KSTR 72                      // halfs per K/V row (64 + 8 pad)
#define KVH  (64 * KSTR)             // 4608 halfs per tensor
#define FBH  (2 * KVH)               // 9216 halfs per stage (K + V)
#define NKT  (TSEQ / 64)
#define FLASH_SMEM (3 * FBH * 2)     // 55296 B

__global__ __launch_bounds__(128, 4) void flash_f16_kernel(
    const __half* __restrict__ qkv, __half* __restrict__ out)
{
    extern __shared__ __half fsm[];
    const uint32_t smb = (uint32_t)__cvta_generic_to_shared(fsm);

    const int b   = blockIdx.z;
    const int h   = blockIdx.y;
    const int q0  = blockIdx.x * 64;
    const int tid = threadIdx.x;
    const int w    = tid >> 5;
    const int lane = tid & 31;
    const int g    = lane >> 2;
    const int tig  = lane & 3;

    #define STAGE_KV(buf_idx, kt)                                              \
        do {                                                                   \
            const uint32_t kb_ = smb + (uint32_t)((buf_idx) * FBH * 2);        \
            const uint32_t vb_ = kb_ + (uint32_t)(KVH * 2);                    \
            for (int i = tid; i < 512; i += 128) {                             \
                const int row = i >> 3;                                        \
                const int c8  = (i & 7) << 3;                                  \
                const size_t base =                                            \
                    ((size_t)(b * TSEQ + (kt) + row)) * QKVN + h * HDIM + c8;  \
                cpa16(kb_ + (uint32_t)((row * KSTR + c8) * 2),                 \
                      &qkv[base + CDIM]);                                      \
                cpa16(vb_ + (uint32_t)((row * KSTR + c8) * 2),                 \
                      &qkv[base + 2 * CDIM]);                                  \
            }                                                                  \
        } while (0)

    // Overlap first K/V stages with Q prep
    STAGE_KV(0, 0);   CP_COMMIT();
    STAGE_KV(1, 64);  CP_COMMIT();

    // ---- stage Q through stage-buffer 2 (overwritten only at iter 0's
    //      STAGE(2), which is after the pre-loop sync) ----
    {
        __half* qs = fsm + 2 * FBH;
        for (int i = tid; i < 512; i += 128) {
            const int row = i >> 3;
            const int c8  = (i & 7) << 3;
            *(uint4*)&qs[row * KSTR + c8] =
                *(const uint4*)&qkv[((size_t)(b * TSEQ + q0 + row)) * QKVN + h * HDIM + c8];
        }
    }
    __syncthreads();

    const int lrow = lane & 15;
    const int lhi8 = (lane >> 4) << 3;
    uint32_t qf[4][4];
    {
        const uint32_t qb = smb + (uint32_t)(2 * FBH * 2) +
                            (uint32_t)(((w * 16 + lrow) * KSTR + lhi8) * 2);
        #pragma unroll
        for (int ds = 0; ds < 4; ds++) ldsm4(qf[ds], qb + (uint32_t)(ds * 32));
    }

    CP_WAITG(1);        // stage 0 landed (per-thread)
    __syncthreads();    // visible to all; everyone's Q ldsm done -> buf2 free

    const int krow_off = ((lane >> 4) << 3) + (lane & 7);
    const int kdsel    = ((lane >> 3) & 1) << 3;
    const int vrow_off = (((lane >> 3) & 1) << 3) + (lane & 7);
    const int vdsel    = (lane >> 4) << 3;

    float o[8][4];
    #pragma unroll
    for (int nt = 0; nt < 8; nt++)
        #pragma unroll
        for (int i = 0; i < 4; i++) o[nt][i] = 0.0f;
    float m0 = -1e30f, m1 = -1e30f, l0 = 0.0f, l1 = 0.0f;

    for (int it = 0; it < NKT; it++) {
        if (it + 2 < NKT) STAGE_KV((it + 2) % 3, (it + 2) * 64);
        CP_COMMIT();    // always commit to keep group accounting fixed

        const uint32_t ksb = smb + (uint32_t)((it % 3) * FBH * 2);
        const uint32_t vsb = ksb + (uint32_t)(KVH * 2);
        const uint32_t kbase = ksb + (uint32_t)((krow_off * KSTR + kdsel) * 2);
        const uint32_t vbase = vsb + (uint32_t)((vrow_off * KSTR + vdsel) * 2);

        // ---- S = Q @ K^T (base-2 logits) ----
        float sv[8][4];
        #pragma unroll
        for (int nt = 0; nt < 8; nt++)
            #pragma unroll
            for (int i = 0; i < 4; i++) sv[nt][i] = 0.0f;

        #pragma unroll
        for (int ds = 0; ds < 4; ds++) {
            #pragma unroll
            for (int j = 0; j < 4; j++) {
                uint32_t bf[4];
                ldsm4(bf, kbase + (uint32_t)((j * 16 * KSTR + ds * 16) * 2));
                mma16(sv[2 * j],     qf[ds], bf);
                mma16(sv[2 * j + 1], qf[ds], bf + 2);
            }
        }

        // ---- online softmax in exp2 domain (rows g and g+8) ----
        float rmax0 = -1e30f, rmax1 = -1e30f;
        #pragma unroll
        for (int nt = 0; nt < 8; nt++) {
            rmax0 = fmaxf(rmax0, fmaxf(sv[nt][0], sv[nt][1]));
            rmax1 = fmaxf(rmax1, fmaxf(sv[nt][2], sv[nt][3]));
        }
        rmax0 = fmaxf(rmax0, __shfl_xor_sync(0xffffffffu, rmax0, 1));
        rmax0 = fmaxf(rmax0, __shfl_xor_sync(0xffffffffu, rmax0, 2));
        rmax1 = fmaxf(rmax1, __shfl_xor_sync(0xffffffffu, rmax1, 1));
        rmax1 = fmaxf(rmax1, __shfl_xor_sync(0xffffffffu, rmax1, 2));

        const float mn0 = fmaxf(m0, rmax0);
        const float mn1 = fmaxf(m1, rmax1);
        const float cr0 = exp2f(m0 - mn0);
        const float cr1 = exp2f(m1 - mn1);
        m0 = mn0; m1 = mn1;

        float ls0 = 0.0f, ls1 = 0.0f;
        uint32_t pv[8][2];
        #pragma unroll
        for (int nt = 0; nt < 8; nt++) {
            const float p0 = exp2f(sv[nt][0] - mn0);
            const float p1 = exp2f(sv[nt][1] - mn0);
            const float p2 = exp2f(sv[nt][2] - mn1);
            const float p3 = exp2f(sv[nt][3] - mn1);
            ls0 += p0 + p1;  ls1 += p2 + p3;
            pv[nt][0] = packh2(p0, p1);   // P C-frag == PV A-frag layout
            pv[nt][1] = packh2(p2, p3);
        }
        ls0 += __shfl_xor_sync(0xffffffffu, ls0, 1);
        ls0 += __shfl_xor_sync(0xffffffffu, ls0, 2);
        ls1 += __shfl_xor_sync(0xffffffffu, ls1, 1);
        ls1 += __shfl_xor_sync(0xffffffffu, ls1, 2);
        l0 = l0 * cr0 + ls0;
        l1 = l1 * cr1 + ls1;

        #pragma unroll
        for (int nt = 0; nt < 8; nt++) {
            o[nt][0] *= cr0; o[nt][1] *= cr0;
            o[nt][2] *= cr1; o[nt][3] *= cr1;
        }

        // ---- O += P @ V ----
        #pragma unroll
        for (int j = 0; j < 4; j++) {
            const uint32_t a[4] = { pv[2 * j][0], pv[2 * j][1],
                                    pv[2 * j + 1][0], pv[2 * j + 1][1] };
            #pragma unroll
            for (int t = 0; t < 4; t++) {
                uint32_t bf[4];
                ldsm4t(bf, vbase + (uint32_t)((j * 16 * KSTR + t * 16) * 2));
                mma16(o[2 * t],     a, bf);
                mma16(o[2 * t + 1], a, bf + 2);
            }
        }

        CP_WAITG(1);        // stage it+1 landed (per-thread)
        __syncthreads();    // single barrier: visibility + buffer-reuse order
    }
    #undef STAGE_KV

    // ---- epilogue: fp16 att for proj GEMM ----
    const float i0 = 1.0f / l0;
    const float i1 = 1.0f / l1;
    const int r0 = q0 + w * 16 + g;
    #pragma unroll
    for (int nt = 0; nt < 8; nt++) {
        const int cc = h * HDIM + nt * 8 + 2 * tig;
        *(uint32_t*)&out[((size_t)(b * TSEQ + r0)) * CDIM + cc] =
            packh2(o[nt][0] * i0, o[nt][1] * i0);
        *(uint32_t*)&out[((size_t)(b * TSEQ + r0 + 8)) * CDIM + cc] =
            packh2(o[nt][2] * i1, o[nt][3] * i1);
    }
}

// ---------------------------------------------------------------------------
// Launch
// ---------------------------------------------------------------------------
extern "C" void kernel_launch(void* const* d_in, const int* in_sizes, int n_in,
                              void* d_out, int out_size)
{
    const float* x      = (const float*)d_in[0];
    const float* w_qkv  = (const float*)d_in[1];
    const float* b_qkv  = (const float*)d_in[2];
    const float* w_proj = (const float*)d_in[3];
    const float* b_proj = (const float*)d_in[4];
    float* out = (float*)d_out;

    __half* qkv;   cudaGetSymbolAddress((void**)&qkv,   g_qkv);
    __half* att;   cudaGetSymbolAddress((void**)&att,   g_att);
    __half* xh;    cudaGetSymbolAddress((void**)&xh,    g_xh);
    __half* wqkvh; cudaGetSymbolAddress((void**)&wqkvh, g_wqkvh);
    __half* wprjh; cudaGetSymbolAddress((void**)&wprjh, g_wprojh);

    cudaFuncSetAttribute(gemm_f16_kernel,
                         cudaFuncAttributeMaxDynamicSharedMemorySize, GEMM_SMEM);
    cudaFuncSetAttribute(flash_f16_kernel,
                         cudaFuncAttributeMaxDynamicSharedMemorySize, FLASH_SMEM);

    const int M = BATCH * TSEQ;   // 4096

    // 0) fused fp16 pre-conversion (one launch for x, w_qkv, w_proj)
    {
        const int total8 = N8X + N8Q + N8P;   // 1048576
        f16_convert_all_kernel<<<(total8 + 255) / 256, 256>>>(
            x, w_qkv, w_proj, xh, wqkvh, wprjh);
    }
    {   // 1) QKV projection (fp16 out, Q pre-scaled incl. log2e)
        dim3 grid(QKVN / 128, M / 128);   // (24, 32)
        gemm_f16_kernel<<<grid, 256, GEMM_SMEM>>>(xh, wqkvh, b_qkv, qkv, M, QKVN, CDIM, 1);
    }
    {   // 2) Flash attention (fp16 mma.sync, 4 CTAs/SM occupancy target)
        dim3 grid(TSEQ / 64, NHEADS, BATCH);   // (32, 16, 2)
        flash_f16_kernel<<<grid, 128, FLASH_SMEM>>>(qkv, att);
    }
    {   // 3) Output projection (fp32 out)
        dim3 grid(CDIM / 128, M / 128);   // (8, 32)
        gemm_f16_kernel<<<grid, 256, GEMM_SMEM>>>(att, wprjh, b_proj, out, M, CDIM, CDIM, 0);
    }
}